// round 5
// baseline (speedup 1.0000x reference)
#include <cuda_runtime.h>
#include <math.h>

#define W_   512
#define H_   512
#define HW_  (512 * 512)
#define EPS  1e-8f
#define TW   26              // output columns per warp (26 + 6 halo = 32 lanes)
#define FULLMASK 0xffffffffu

__device__ __forceinline__ float sqrt_approx(float x) {
    float r;
    asm("sqrt.approx.f32 %0, %1;" : "=f"(r) : "f"(x));
    return r;
}

// h[L] = sum_{k=0..6} v[L+k] over the warp-distributed 32-vector.
// Lanes >= 26 get garbage (shfl self) — outputs there are predicated off.
__device__ __forceinline__ float hsum7(float v) {
    float d1 = v + __shfl_down_sync(FULLMASK, v, 1);     // 2-sum
    float d2 = d1 + __shfl_down_sync(FULLMASK, d1, 2);   // 4-sum
    float r4 = __shfl_down_sync(FULLMASK, d1, 4);        // v[c+4]+v[c+5]
    float r6 = __shfl_down_sync(FULLMASK, v, 6);         // v[c+6]
    return d2 + (r4 + r6);
}

__device__ __forceinline__ float smooth_l1(float a, float b) {
    float d = a - b;
    float ad = fabsf(d);
    return (ad < 1.0f) ? 0.5f * d * d : ad - 0.5f;
}

// One input row: predicated loads (3 ch x 2 inputs), channel reduce,
// horizontal 7-sum via shuffles, vertical running sum where the value from
// 7 rows ago comes from pre[] (prefetched from the SMEM ring LAST row, so
// LDS latency is fully hidden). Then store h to ring slot S and prefetch
// slot (S+1)%7 for the next row. Emit smooth-L1 once warmed up (i >= 6).
template <int S>
__device__ __forceinline__ void rowstep(
    const float* __restrict__ P, const float* __restrict__ T,
    int gx, bool okx, bool out_ok, int oy0,
    int& i, float4* ringLane, float (&pre)[4], float (&vs)[4],
    float& acc, float inv_n)
{
    const int gy = oy0 - 3 + i;
    const bool ok = okx && (gy >= 0) && (gy < H_);
    const int off = (gy << 9) + gx;

    float h0, h1, h2, h3;
    {
        float a0 = ok ? P[off]           : 0.f;
        float a1 = ok ? P[off + HW_]     : 0.f;
        float a2 = ok ? P[off + 2 * HW_] : 0.f;
        float v  = a0 + a1 + a2;
        float v2 = fmaf(a0, a0, fmaf(a1, a1, a2 * a2));
        h0 = hsum7(v);
        h1 = hsum7(v2);
    }
    {
        float a0 = ok ? T[off]           : 0.f;
        float a1 = ok ? T[off + HW_]     : 0.f;
        float a2 = ok ? T[off + 2 * HW_] : 0.f;
        float v  = a0 + a1 + a2;
        float v2 = fmaf(a0, a0, fmaf(a1, a1, a2 * a2));
        h2 = hsum7(v);
        h3 = hsum7(v2);
    }

    vs[0] += h0 - pre[0];
    vs[1] += h1 - pre[1];
    vs[2] += h2 - pre[2];
    vs[3] += h3 - pre[3];

    ringLane[S * 32] = make_float4(h0, h1, h2, h3);   // STS.128, lane-private
    float4 nx = ringLane[((S + 1) % 7) * 32];         // prefetch next row's old value
    pre[0] = nx.x; pre[1] = nx.y; pre[2] = nx.z; pre[3] = nx.w;

    if (i >= 6 && out_ok) {
        float mp = vs[0] * inv_n;
        float sp = sqrt_approx(fmaf(-mp, mp, vs[1] * inv_n) + EPS);
        float mt = vs[2] * inv_n;
        float st = sqrt_approx(fmaf(-mt, mt, vs[3] * inv_n) + EPS);
        acc += smooth_l1(sp, st);
    }
    i++;
}

__global__ __launch_bounds__(128, 8)
void dist_loss_kernel(const float* __restrict__ pred,
                      const float* __restrict__ tgt,
                      float* __restrict__ out)
{
    __shared__ float4 ring_s[4][7][32];   // [warp][slot][lane], lane-private
    __shared__ float  wsum[4];

    const int L  = threadIdx.x & 31;
    const int w  = threadIdx.x >> 5;
    const int x0 = blockIdx.x * TW;
    const int oy0 = (blockIdx.y << 7) + (w << 5);     // warp's first output row
    const size_t bofs = (size_t)blockIdx.z * 3 * HW_;
    const float* P = pred + bofs;
    const float* T = tgt + bofs;

    const int gx = x0 - 3 + L;                        // halo-inclusive column
    const bool okx = (gx >= 0) && (gx < W_);
    const bool out_ok = (L < TW) && ((x0 + L) < W_);

    const float inv_n = 1.0f / 147.0f;

    float4* ringLane = &ring_s[w][0][L];
#pragma unroll
    for (int s = 0; s < 7; s++)
        ringLane[s * 32] = make_float4(0.f, 0.f, 0.f, 0.f);

    float pre[4] = {0.f, 0.f, 0.f, 0.f};
    float vs[4]  = {0.f, 0.f, 0.f, 0.f};

    float acc = 0.f;
    int i = 0;

    // 38 input rows = 5 chunks of 7 ring slots + 3 tail steps
#pragma unroll 1
    for (int c = 0; c < 5; c++) {
        rowstep<0>(P, T, gx, okx, out_ok, oy0, i, ringLane, pre, vs, acc, inv_n);
        rowstep<1>(P, T, gx, okx, out_ok, oy0, i, ringLane, pre, vs, acc, inv_n);
        rowstep<2>(P, T, gx, okx, out_ok, oy0, i, ringLane, pre, vs, acc, inv_n);
        rowstep<3>(P, T, gx, okx, out_ok, oy0, i, ringLane, pre, vs, acc, inv_n);
        rowstep<4>(P, T, gx, okx, out_ok, oy0, i, ringLane, pre, vs, acc, inv_n);
        rowstep<5>(P, T, gx, okx, out_ok, oy0, i, ringLane, pre, vs, acc, inv_n);
        rowstep<6>(P, T, gx, okx, out_ok, oy0, i, ringLane, pre, vs, acc, inv_n);
    }
    rowstep<0>(P, T, gx, okx, out_ok, oy0, i, ringLane, pre, vs, acc, inv_n);
    rowstep<1>(P, T, gx, okx, out_ok, oy0, i, ringLane, pre, vs, acc, inv_n);
    rowstep<2>(P, T, gx, okx, out_ok, oy0, i, ringLane, pre, vs, acc, inv_n);

    // warp + block reduce
#pragma unroll
    for (int o = 16; o > 0; o >>= 1)
        acc += __shfl_xor_sync(FULLMASK, acc, o);
    if (L == 0) wsum[w] = acc;
    __syncthreads();
    if (threadIdx.x == 0) {
        float s = wsum[0] + wsum[1] + wsum[2] + wsum[3];
        atomicAdd(out, s * (1.0f / (16.0f * 512.0f * 512.0f)));
    }
}

extern "C" void kernel_launch(void* const* d_in, const int* in_sizes, int n_in,
                              void* d_out, int out_size)
{
    const float* pred = (const float*)d_in[0];
    const float* tgt  = (const float*)d_in[1];
    float* out = (float*)d_out;

    cudaMemsetAsync(out, 0, sizeof(float));

    dim3 block(128, 1, 1);
    dim3 grid((W_ + TW - 1) / TW, H_ / 128, 16);   // 20 x 4 x 16 = 1280 CTAs
    dist_loss_kernel<<<grid, block>>>(pred, tgt, out);
}